// round 16
// baseline (speedup 1.0000x reference)
#include <cuda_runtime.h>

// Problem dims
#define Td 256
#define Bd 512
#define Ed 256
#define Hd 256
#define Cd 256
#define Nd 128
#define Vd 256
#define Od 256
#define EPSf 1e-8f

#define BT   4            // batch rows per CTA
#define NCTA (Bd/BT)      // 128 CTAs
#define NTH  1024         // threads per CTA (32 warps)
#define NWARP (NTH/32)

typedef unsigned long long u64;

// Packed f32x2 ops (sm_103a): 2 fp32 MACs per issue slot on the fma pipe.
#define FMA2(d, a, b, c) \
    asm("fma.rn.f32x2 %0, %1, %2, %3;" : "=l"(d) : "l"(a), "l"(b), "l"(c))
#define MUL2(d, a, b) \
    asm("mul.rn.f32x2 %0, %1, %2;" : "=l"(d) : "l"(a), "l"(b))
#define PK2(d, lo, hi) \
    asm("mov.b64 %0, {%1, %2};" : "=l"(d) : "f"(lo), "f"(hi))
#define UPK2(lo, hi, s) \
    asm("mov.b64 {%0, %1}, %2;" : "=f"(lo), "=f"(hi) : "l"(s))

// 64MB NTM memory state scratch (allowed: __device__ global array)
__device__ float g_mem[(size_t)Bd * Nd * Vd];

// Dynamic smem (~113KB)
struct SM {
    float4 scratch[4096];          // 64KB: GEMM partials / readout partials
    float4 ciT[Ed + Vd];           // 8KB : transposed [x_t | read]
    float4 hT [Hd];                // 4KB : transposed hidden
    float4 woT0[Cd + Vd];          // 8KB : transposed [co | r], ping
    float4 woT1[Cd + Vd];          // 8KB : transposed [co | r], pong
    float  k [BT][Vd];             // 4KB
    float  o [BT][2 * Vd];         // 8KB : [kw | v]
    float  ww[BT][Nd];             // 2KB : raw write-address scores
    float  wwprev[BT][Nd];         // 2KB : normalized write weights (pending)
    float  vprev[BT][Vd];          // 4KB : pending update value vector
    float  pM[BT][4], pZ[BT][4];   // online-softmax partials (4 j-groups)
    float  coef[BT][4];
    float  invZ[BT];
};

__device__ __forceinline__ float wsum(float v) {
    #pragma unroll
    for (int o = 16; o; o >>= 1) v += __shfl_xor_sync(0xffffffffu, v, o);
    return v;
}
__device__ __forceinline__ float wmax(float v) {
    #pragma unroll
    for (int o = 16; o; o >>= 1) v = fmaxf(v, __shfl_xor_sync(0xffffffffu, v, o));
    return v;
}

// Register-tiled K-sliced GEMM main pass, f32x2 accumulators. NO internal
// sync — caller syncs. ltid in [0, THR). Each weight float4 loaded once.
template<int KC, int NC, int THR>
__device__ __forceinline__ void gemm_main(int ltid,
                                          const float4* __restrict__ actT,
                                          const float* __restrict__ W,
                                          const float* __restrict__ bias,
                                          float4* __restrict__ scratch)
{
    constexpr int CG = NC / 4;
    constexpr int KS = THR / CG;
    constexpr int KL = KC / KS;
    const int ks = ltid / CG;
    const int cg = ltid - ks * CG;

    const ulonglong2* wq = (const ulonglong2*)(W + (size_t)(ks * KL) * NC) + cg;
    const float4* ap = actT + ks * KL;

    u64 a01[BT], a23[BT];
    if (ks == 0) {
        ulonglong2 b = __ldg((const ulonglong2*)bias + cg);
        #pragma unroll
        for (int r = 0; r < BT; r++) { a01[r] = b.x; a23[r] = b.y; }
    } else {
        #pragma unroll
        for (int r = 0; r < BT; r++) { a01[r] = 0ull; a23[r] = 0ull; }
    }

    #pragma unroll 4
    for (int kk = 0; kk < KL; kk++) {
        float4 av = ap[kk];                                // LDS.128 broadcast
        ulonglong2 wv = __ldg(wq + (size_t)kk * (NC / 4)); // LDG.128 = 2 f32x2
        u64 aa;
        PK2(aa, av.x, av.x); FMA2(a01[0], aa, wv.x, a01[0]); FMA2(a23[0], aa, wv.y, a23[0]);
        PK2(aa, av.y, av.y); FMA2(a01[1], aa, wv.x, a01[1]); FMA2(a23[1], aa, wv.y, a23[1]);
        PK2(aa, av.z, av.z); FMA2(a01[2], aa, wv.x, a01[2]); FMA2(a23[2], aa, wv.y, a23[2]);
        PK2(aa, av.w, av.w); FMA2(a01[3], aa, wv.x, a01[3]); FMA2(a23[3], aa, wv.y, a23[3]);
    }
    #pragma unroll
    for (int r = 0; r < BT; r++)
        ((ulonglong2*)scratch)[(ks * BT + r) * CG + cg] = make_ulonglong2(a01[r], a23[r]);
}

// Combine K-slice partials. task in [0, BT*NC/4). MODE 0: row-major smem.
// MODE 1: transposed smem. MODE 2: row-major global (rstride).
template<int NC, int KS, bool RELU, int MODE>
__device__ __forceinline__ void gemm_combine(int task,
                                             const float4* __restrict__ scratch,
                                             float* __restrict__ dst,
                                             float4* __restrict__ dstT,
                                             size_t rstride)
{
    constexpr int CG = NC / 4;
    const int row = task / CG, cg = task - row * CG;
    float4 v = scratch[row * CG + cg];
    #pragma unroll
    for (int ks = 1; ks < KS; ks++) {
        float4 p = scratch[(ks * BT + row) * CG + cg];
        v.x += p.x; v.y += p.y; v.z += p.z; v.w += p.w;
    }
    if (RELU) {
        v.x = fmaxf(v.x, 0.f); v.y = fmaxf(v.y, 0.f);
        v.z = fmaxf(v.z, 0.f); v.w = fmaxf(v.w, 0.f);
    }
    if (MODE == 0) {
        *(float4*)(dst + row * NC + cg * 4) = v;
    } else if (MODE == 1) {
        ((float*)(dstT + cg * 4 + 0))[row] = v.x;
        ((float*)(dstT + cg * 4 + 1))[row] = v.y;
        ((float*)(dstT + cg * 4 + 2))[row] = v.z;
        ((float*)(dstT + cg * 4 + 3))[row] = v.w;
    } else {
        *(float4*)(dst + (size_t)row * rstride + cg * 4) = v;
    }
}

__global__ void __launch_bounds__(NTH, 1) ntm_kernel(
    const float* __restrict__ x,
    const float* __restrict__ W1, const float* __restrict__ b1,
    const float* __restrict__ W2, const float* __restrict__ b2,
    const float* __restrict__ Wr, const float* __restrict__ br,
    const float* __restrict__ Ww, const float* __restrict__ bw,
    const float* __restrict__ Wo, const float* __restrict__ bo,
    const float* __restrict__ init_read,
    const float* __restrict__ mem0,
    float* __restrict__ out)
{
    extern __shared__ char smraw[];
    SM& s = *reinterpret_cast<SM*>(smraw);

    const int tid  = threadIdx.x;
    const int b0   = blockIdx.x * BT;
    const int wid  = tid >> 5, lane = tid & 31;

    // ---- init: mem slice, zero pending, stage init_read + x_0 ----
    {
        const float4* src = (const float4*)(mem0 + (size_t)b0 * Nd * Vd);
        float4*       dst = (float4*)(g_mem + (size_t)b0 * Nd * Vd);
        for (int i = tid; i < BT * Nd * Vd / 4; i += NTH) dst[i] = src[i];
        if (tid < BT * Nd) ((float*)s.wwprev)[tid] = 0.f;
        if (tid < BT * Vd / 4) {
            ((float4*)s.vprev)[tid] = make_float4(0.f, 0.f, 0.f, 0.f);
            int r = tid >> 6, c4 = tid & 63;
            float4 v = __ldg((const float4*)(init_read + (size_t)(b0 + r) * Vd) + c4);
            ((float*)(s.ciT + Ed + c4 * 4 + 0))[r] = v.x;
            ((float*)(s.ciT + Ed + c4 * 4 + 1))[r] = v.y;
            ((float*)(s.ciT + Ed + c4 * 4 + 2))[r] = v.z;
            ((float*)(s.ciT + Ed + c4 * 4 + 3))[r] = v.w;
        } else if (tid >= 512 && tid < 768) {
            int idx = tid - 512;
            int r = idx >> 6, c4 = idx & 63;
            float4 v = __ldg((const float4*)(x + (size_t)(b0 + r) * Ed) + c4);
            ((float*)(s.ciT + c4 * 4 + 0))[r] = v.x;
            ((float*)(s.ciT + c4 * 4 + 1))[r] = v.y;
            ((float*)(s.ciT + c4 * 4 + 2))[r] = v.z;
            ((float*)(s.ciT + c4 * 4 + 3))[r] = v.w;
        }
    }
    __syncthreads();

    for (int t = 0; t < Td; t++) {
        float4* woCur  = (t & 1) ? s.woT1 : s.woT0;
        float4* woPrev = (t & 1) ? s.woT0 : s.woT1;

        // ---- P1: h = relu(ci @ W1 + b1), all 1024 threads ----
        gemm_main<Ed + Vd, Hd, NTH>(tid, s.ciT, W1, b1, s.scratch);
        __syncthreads();

        // ---- P2: combine h (+relu) ----
        if (tid < 256)
            gemm_combine<Hd, 16, true, 1>(tid, s.scratch, nullptr, s.hT, 0);
        __syncthreads();

        // ---- P3: co = h @ W2 + b2 (full width) -> woCur[0..Cd) ----
        gemm_main<Hd, Cd, NTH>(tid, s.hT, W2, b2, s.scratch);
        __syncthreads();
        if (tid < 256)
            gemm_combine<Cd, 16, false, 1>(tid, s.scratch, nullptr, woCur, 0);
        __syncthreads();

        // ---- P4: k = co @ Wr (thr 0-511) || o = co @ Ww (thr 512-1023) ----
        if (tid < 512)
            gemm_main<Cd, Vd, 512>(tid, woCur, Wr, br, s.scratch);
        else
            gemm_main<Cd, 2 * Vd, 512>(tid - 512, woCur, Ww, bw, s.scratch + 2048);
        __syncthreads();

        // ---- P5: combine k | combine o ----
        if (tid < 256)
            gemm_combine<Vd, 8, false, 0>(tid, s.scratch, &s.k[0][0], nullptr, 0);
        else if (tid < 768)
            gemm_combine<2 * Vd, 4, false, 0>(tid - 256, s.scratch + 2048, &s.o[0][0], nullptr, 0);
        __syncthreads();

        // ==== P6: WARP-SPECIALIZED: warps 0-15 fused mem pass (f32x2)
        //          || warps 16-31 Wo GEMM on woPrev (t > 0). ====
        if (wid < 16) {
            const int r = wid >> 2, j = wid & 3;     // warp: row r, j-group of 4
            const ulonglong2* k2 = (const ulonglong2*)s.k[r];
            const ulonglong2* q2 = (const ulonglong2*)s.o[r];
            const ulonglong2* v2 = (const ulonglong2*)s.vprev[r];
            ulonglong2 kA = k2[lane], kB = k2[lane + 32];
            ulonglong2 qA = q2[lane], qB = q2[lane + 32];
            ulonglong2 vA = v2[lane], vB = v2[lane + 32];

            // in-warp key norms (replicated across j-warps; barrier-free)
            float knr, kwnr;
            {
                u64 n2 = 0ull;
                FMA2(n2, kA.x, kA.x, n2); FMA2(n2, kA.y, kA.y, n2);
                FMA2(n2, kB.x, kB.x, n2); FMA2(n2, kB.y, kB.y, n2);
                float lo, hi; UPK2(lo, hi, n2);
                knr = fmaxf(sqrtf(wsum(lo + hi)), EPSf);
                n2 = 0ull;
                FMA2(n2, qA.x, qA.x, n2); FMA2(n2, qA.y, qA.y, n2);
                FMA2(n2, qB.x, qB.x, n2); FMA2(n2, qB.y, qB.y, n2);
                UPK2(lo, hi, n2);
                kwnr = fmaxf(sqrtf(wsum(lo + hi)), EPSf);
            }

            float M = -1e30f, Z = 0.f;
            u64 r0 = 0ull, r1 = 0ull, r2 = 0ull, r3 = 0ull;
            ulonglong2* gm = (ulonglong2*)(g_mem + (size_t)(b0 + r) * Nd * Vd);

            #pragma unroll 2
            for (int i = 0; i < Nd / 4; i++) {       // 32 slots per warp
                const int n = j + 4 * i;
                ulonglong2* mp = gm + (size_t)n * (Vd / 4);
                ulonglong2 m0 = mp[lane], m1 = mp[lane + 32];
                float wp = s.wwprev[r][n];
                u64 wp2; PK2(wp2, wp, wp);
                FMA2(m0.x, wp2, vA.x, m0.x); FMA2(m0.y, wp2, vA.y, m0.y);
                FMA2(m1.x, wp2, vB.x, m1.x); FMA2(m1.y, wp2, vB.y, m1.y);
                mp[lane] = m0; mp[lane + 32] = m1;

                u64 dk2 = 0ull, dw2 = 0ull, nn2 = 0ull;
                FMA2(dk2, m0.x, kA.x, dk2); FMA2(dk2, m0.y, kA.y, dk2);
                FMA2(dk2, m1.x, kB.x, dk2); FMA2(dk2, m1.y, kB.y, dk2);
                FMA2(dw2, m0.x, qA.x, dw2); FMA2(dw2, m0.y, qA.y, dw2);
                FMA2(dw2, m1.x, qB.x, dw2); FMA2(dw2, m1.y, qB.y, dw2);
                FMA2(nn2, m0.x, m0.x, nn2); FMA2(nn2, m0.y, m0.y, nn2);
                FMA2(nn2, m1.x, m1.x, nn2); FMA2(nn2, m1.y, m1.y, nn2);
                float lo, hi, dk, dw, nn;
                UPK2(lo, hi, dk2); dk = lo + hi;
                UPK2(lo, hi, dw2); dw = lo + hi;
                UPK2(lo, hi, nn2); nn = lo + hi;
                dk = wsum(dk); dw = wsum(dw); nn = wsum(nn);

                float mn = fmaxf(sqrtf(nn), EPSf);
                float sk = dk / (knr * mn);
                float sw = dw / (kwnr * mn);
                if (!lane) s.ww[r][n] = sw;

                float nM = fmaxf(M, sk);
                float sc = __expf(M - nM);
                float e  = __expf(sk - nM);
                Z = fmaf(Z, sc, e);
                u64 sc2, e2, tt;
                PK2(sc2, sc, sc); PK2(e2, e, e);
                MUL2(tt, e2, m0.x); FMA2(r0, r0, sc2, tt);
                MUL2(tt, e2, m0.y); FMA2(r1, r1, sc2, tt);
                MUL2(tt, e2, m1.x); FMA2(r2, r2, sc2, tt);
                MUL2(tt, e2, m1.y); FMA2(r3, r3, sc2, tt);
                M = nM;
            }
            ((ulonglong2*)s.scratch)[(r * 4 + j) * 64 + lane]      = make_ulonglong2(r0, r1);
            ((ulonglong2*)s.scratch)[(r * 4 + j) * 64 + lane + 32] = make_ulonglong2(r2, r3);
            if (!lane) { s.pM[r][j] = M; s.pZ[r][j] = Z; }
        } else if (t > 0) {
            // out_{t-1} = [co|r]_{t-1} @ Wo + bo, main pass on woPrev
            gemm_main<Cd + Vd, Od, 512>(tid - 512, woPrev, Wo, bo, s.scratch + 2048);
        }
        __syncthreads();

        // ---- P7: merge online-softmax partial scales (warp 0, 4 groups) ----
        if (wid == 0) {
            int r = (lane >> 2) & 3, j = lane & 3;   // lanes 16-31 duplicate
            float m = s.pM[r][j];
            float mm = m;
            mm = fmaxf(mm, __shfl_xor_sync(0xffffffffu, mm, 1));
            mm = fmaxf(mm, __shfl_xor_sync(0xffffffffu, mm, 2));
            float cf = __expf(m - mm);
            float zs = cf * s.pZ[r][j];
            zs += __shfl_xor_sync(0xffffffffu, zs, 1);
            zs += __shfl_xor_sync(0xffffffffu, zs, 2);
            s.coef[r][j] = cf;
            if (j == 0) s.invZ[r] = 1.f / zs;
        }
        __syncthreads();

        // ---- P8: r-combine | ww softmax | vprev | out-combine | stage x ----
        if (tid < BT * Vd / 4) {
            int r = tid >> 6, c4 = tid & 63;
            float4 acc = make_float4(0.f, 0.f, 0.f, 0.f);
            #pragma unroll
            for (int j = 0; j < 4; j++) {
                float cf = s.coef[r][j];
                float4 p = s.scratch[(r * 4 + j) * 64 + c4];
                acc.x = fmaf(cf, p.x, acc.x); acc.y = fmaf(cf, p.y, acc.y);
                acc.z = fmaf(cf, p.z, acc.z); acc.w = fmaf(cf, p.w, acc.w);
            }
            float iz = s.invZ[r];
            acc.x *= iz; acc.y *= iz; acc.z *= iz; acc.w *= iz;
            ((float*)(woCur + Cd + c4 * 4 + 0))[r] = acc.x;
            ((float*)(woCur + Cd + c4 * 4 + 1))[r] = acc.y;
            ((float*)(woCur + Cd + c4 * 4 + 2))[r] = acc.z;
            ((float*)(woCur + Cd + c4 * 4 + 3))[r] = acc.w;
            ((float*)(s.ciT + Ed + c4 * 4 + 0))[r] = acc.x;
            ((float*)(s.ciT + Ed + c4 * 4 + 1))[r] = acc.y;
            ((float*)(s.ciT + Ed + c4 * 4 + 2))[r] = acc.z;
            ((float*)(s.ciT + Ed + c4 * 4 + 3))[r] = acc.w;
        } else if (wid >= 8 && wid < 8 + BT) {
            int r = wid - 8;
            float* rowp = s.ww[r];
            float v0 = rowp[lane], v1 = rowp[lane + 32], v2 = rowp[lane + 64], v3 = rowp[lane + 96];
            float mx = wmax(fmaxf(fmaxf(v0, v1), fmaxf(v2, v3)));
            float e0 = __expf(v0 - mx), e1 = __expf(v1 - mx), e2 = __expf(v2 - mx), e3 = __expf(v3 - mx);
            float sm = wsum(e0 + e1 + e2 + e3);
            float inv = 1.f / sm;
            s.wwprev[r][lane]      = e0 * inv;
            s.wwprev[r][lane + 32] = e1 * inv;
            s.wwprev[r][lane + 64] = e2 * inv;
            s.wwprev[r][lane + 96] = e3 * inv;
        } else if (tid >= 384 && tid < 640) {
            int idx = tid - 384;
            int r = idx >> 6, c4 = idx & 63;
            ((float4*)s.vprev[r])[c4] = ((const float4*)(s.o[r] + Vd))[c4];
        } else if (tid >= 640 && tid < 896) {
            if (t > 0)
                gemm_combine<Od, 8, false, 2>(tid - 640, s.scratch + 2048,
                                              out + ((size_t)(t - 1) * Bd + b0) * Od,
                                              nullptr, (size_t)Od);
        } else if (tid >= 896 && t + 1 < Td) {
            int base = tid - 896;
            #pragma unroll
            for (int q = 0; q < 2; q++) {
                int idx = base + q * 128;
                int r = idx >> 6, c4 = idx & 63;
                float4 v = __ldg((const float4*)(x + ((size_t)(t + 1) * Bd + b0 + r) * Ed) + c4);
                ((float*)(s.ciT + c4 * 4 + 0))[r] = v.x;
                ((float*)(s.ciT + c4 * 4 + 1))[r] = v.y;
                ((float*)(s.ciT + c4 * 4 + 2))[r] = v.z;
                ((float*)(s.ciT + c4 * 4 + 3))[r] = v.w;
            }
        }
        __syncthreads();
    }

    // ---- epilogue: out for t = Td-1 (woT of last step = woT1) ----
    {
        const float4* woLast = ((Td - 1) & 1) ? s.woT1 : s.woT0;
        gemm_main<Cd + Vd, Od, NTH>(tid, woLast, Wo, bo, s.scratch);
        __syncthreads();
        if (tid < 256)
            gemm_combine<Od, 16, false, 2>(tid, s.scratch,
                                           out + ((size_t)(Td - 1) * Bd + b0) * Od,
                                           nullptr, (size_t)Od);
    }
}

extern "C" void kernel_launch(void* const* d_in, const int* in_sizes, int n_in,
                              void* d_out, int out_size)
{
    (void)in_sizes; (void)n_in; (void)out_size;
    const float* x         = (const float*)d_in[0];
    const float* W1        = (const float*)d_in[1];
    const float* b1        = (const float*)d_in[2];
    const float* W2        = (const float*)d_in[3];
    const float* b2        = (const float*)d_in[4];
    const float* Wr        = (const float*)d_in[5];
    const float* br        = (const float*)d_in[6];
    const float* Ww        = (const float*)d_in[7];
    const float* bw        = (const float*)d_in[8];
    const float* Wo        = (const float*)d_in[9];
    const float* bo        = (const float*)d_in[10];
    const float* init_read = (const float*)d_in[11];
    const float* mem0      = (const float*)d_in[12];
    float* out = (float*)d_out;

    int smem = (int)sizeof(SM);
    cudaFuncSetAttribute(ntm_kernel, cudaFuncAttributeMaxDynamicSharedMemorySize, smem);
    ntm_kernel<<<NCTA, NTH, smem>>>(x, W1, b1, W2, b2, Wr, br, Ww, bw, Wo, bo,
                                    init_read, mem0, out);
}

// round 17
// speedup vs baseline: 1.9702x; 1.9702x over previous
#include <cuda_runtime.h>

// Problem dims
#define Td 256
#define Bd 512
#define Ed 256
#define Hd 256
#define Cd 256
#define Nd 128
#define Vd 256
#define Od 256
#define EPSf 1e-8f

#define BT   4            // batch rows per CTA
#define NCTA (Bd/BT)      // 128 CTAs
#define NTH  1024         // threads per CTA (32 warps)
#define NWARP (NTH/32)

typedef unsigned long long u64;

// Packed f32x2 ops (sm_103a): 2 fp32 MACs per issue slot on the fma pipe.
#define FMA2(d, a, b, c) \
    asm("fma.rn.f32x2 %0, %1, %2, %3;" : "=l"(d) : "l"(a), "l"(b), "l"(c))
#define MUL2(d, a, b) \
    asm("mul.rn.f32x2 %0, %1, %2;" : "=l"(d) : "l"(a), "l"(b))
#define PK2(d, lo, hi) \
    asm("mov.b64 %0, {%1, %2};" : "=l"(d) : "f"(lo), "f"(hi))
#define UPK2(lo, hi, s) \
    asm("mov.b64 {%0, %1}, %2;" : "=f"(lo), "=f"(hi) : "l"(s))

// 64MB NTM memory state scratch (allowed: __device__ global array)
__device__ float g_mem[(size_t)Bd * Nd * Vd];

// Dynamic smem (~105KB)
struct SM {
    float4 scratch[4096];          // 64KB: GEMM partials / readout partials
    float4 ciT[Ed + Vd];           // 8KB : transposed [x_t | read]
    float4 hT [Hd];                // 4KB : transposed hidden
    float4 woT[Cd + Vd];           // 8KB : transposed [co | r]
    float  k [BT][Vd];             // 4KB
    float  o [BT][2 * Vd];         // 8KB : [kw | v]
    float  ww[BT][Nd];             // 2KB : raw write-address scores
    float  wwprev[BT][Nd];         // 2KB : normalized write weights (pending)
    float  vprev[BT][Vd];          // 4KB : pending update value vector
    float  pM[BT][8], pZ[BT][8];   // online-softmax partials
    float  coef[BT][8];
    float  invZ[BT];
};

__device__ __forceinline__ float wsum(float v) {
    #pragma unroll
    for (int o = 16; o; o >>= 1) v += __shfl_xor_sync(0xffffffffu, v, o);
    return v;
}
__device__ __forceinline__ float wmax(float v) {
    #pragma unroll
    for (int o = 16; o; o >>= 1) v = fmaxf(v, __shfl_xor_sync(0xffffffffu, v, o));
    return v;
}

// Register-tiled K-sliced GEMM main pass, f32x2 accumulators. NO internal
// sync — caller syncs. ltid in [0, THR). Each weight float4 loaded once.
template<int KC, int NC, int THR>
__device__ __forceinline__ void gemm_main(int ltid,
                                          const float4* __restrict__ actT,
                                          const float* __restrict__ W,
                                          const float* __restrict__ bias,
                                          float4* __restrict__ scratch)
{
    constexpr int CG = NC / 4;
    constexpr int KS = THR / CG;
    constexpr int KL = KC / KS;
    const int ks = ltid / CG;
    const int cg = ltid - ks * CG;

    const ulonglong2* wq = (const ulonglong2*)(W + (size_t)(ks * KL) * NC) + cg;
    const float4* ap = actT + ks * KL;

    u64 a01[BT], a23[BT];
    if (ks == 0) {
        ulonglong2 b = __ldg((const ulonglong2*)bias + cg);
        #pragma unroll
        for (int r = 0; r < BT; r++) { a01[r] = b.x; a23[r] = b.y; }
    } else {
        #pragma unroll
        for (int r = 0; r < BT; r++) { a01[r] = 0ull; a23[r] = 0ull; }
    }

    #pragma unroll 4
    for (int kk = 0; kk < KL; kk++) {
        float4 av = ap[kk];                                // LDS.128 broadcast
        ulonglong2 wv = __ldg(wq + (size_t)kk * (NC / 4)); // LDG.128 = 2 f32x2
        u64 aa;
        PK2(aa, av.x, av.x); FMA2(a01[0], aa, wv.x, a01[0]); FMA2(a23[0], aa, wv.y, a23[0]);
        PK2(aa, av.y, av.y); FMA2(a01[1], aa, wv.x, a01[1]); FMA2(a23[1], aa, wv.y, a23[1]);
        PK2(aa, av.z, av.z); FMA2(a01[2], aa, wv.x, a01[2]); FMA2(a23[2], aa, wv.y, a23[2]);
        PK2(aa, av.w, av.w); FMA2(a01[3], aa, wv.x, a01[3]); FMA2(a23[3], aa, wv.y, a23[3]);
    }
    #pragma unroll
    for (int r = 0; r < BT; r++)
        ((ulonglong2*)scratch)[(ks * BT + r) * CG + cg] = make_ulonglong2(a01[r], a23[r]);
}

// Combine K-slice partials. task in [0, BT*NC/4). MODE 0: row-major smem.
// MODE 1: transposed smem. MODE 2: row-major global (rstride).
template<int NC, int KS, bool RELU, int MODE>
__device__ __forceinline__ void gemm_combine(int task,
                                             const float4* __restrict__ scratch,
                                             float* __restrict__ dst,
                                             float4* __restrict__ dstT,
                                             size_t rstride)
{
    constexpr int CG = NC / 4;
    const int row = task / CG, cg = task - row * CG;
    float4 v = scratch[row * CG + cg];
    #pragma unroll
    for (int ks = 1; ks < KS; ks++) {
        float4 p = scratch[(ks * BT + row) * CG + cg];
        v.x += p.x; v.y += p.y; v.z += p.z; v.w += p.w;
    }
    if (RELU) {
        v.x = fmaxf(v.x, 0.f); v.y = fmaxf(v.y, 0.f);
        v.z = fmaxf(v.z, 0.f); v.w = fmaxf(v.w, 0.f);
    }
    if (MODE == 0) {
        *(float4*)(dst + row * NC + cg * 4) = v;
    } else if (MODE == 1) {
        ((float*)(dstT + cg * 4 + 0))[row] = v.x;
        ((float*)(dstT + cg * 4 + 1))[row] = v.y;
        ((float*)(dstT + cg * 4 + 2))[row] = v.z;
        ((float*)(dstT + cg * 4 + 3))[row] = v.w;
    } else {
        *(float4*)(dst + (size_t)row * rstride + cg * 4) = v;
    }
}

__global__ void __launch_bounds__(NTH, 1) ntm_kernel(
    const float* __restrict__ x,
    const float* __restrict__ W1, const float* __restrict__ b1,
    const float* __restrict__ W2, const float* __restrict__ b2,
    const float* __restrict__ Wr, const float* __restrict__ br,
    const float* __restrict__ Ww, const float* __restrict__ bw,
    const float* __restrict__ Wo, const float* __restrict__ bo,
    const float* __restrict__ init_read,
    const float* __restrict__ mem0,
    float* __restrict__ out)
{
    extern __shared__ char smraw[];
    SM& s = *reinterpret_cast<SM*>(smraw);

    const int tid  = threadIdx.x;
    const int b0   = blockIdx.x * BT;
    const int wid  = tid >> 5, lane = tid & 31;

    // ---- init: mem slice, zero pending, stage init_read + x_0 ----
    {
        const float4* src = (const float4*)(mem0 + (size_t)b0 * Nd * Vd);
        float4*       dst = (float4*)(g_mem + (size_t)b0 * Nd * Vd);
        for (int i = tid; i < BT * Nd * Vd / 4; i += NTH) dst[i] = src[i];
        if (tid < BT * Nd) ((float*)s.wwprev)[tid] = 0.f;
        if (tid < BT * Vd / 4) {
            ((float4*)s.vprev)[tid] = make_float4(0.f, 0.f, 0.f, 0.f);
            int r = tid >> 6, c4 = tid & 63;
            float4 v = __ldg((const float4*)(init_read + (size_t)(b0 + r) * Vd) + c4);
            ((float*)(s.ciT + Ed + c4 * 4 + 0))[r] = v.x;
            ((float*)(s.ciT + Ed + c4 * 4 + 1))[r] = v.y;
            ((float*)(s.ciT + Ed + c4 * 4 + 2))[r] = v.z;
            ((float*)(s.ciT + Ed + c4 * 4 + 3))[r] = v.w;
        } else if (tid >= 512 && tid < 768) {
            int idx = tid - 512;
            int r = idx >> 6, c4 = idx & 63;
            float4 v = __ldg((const float4*)(x + (size_t)(b0 + r) * Ed) + c4);
            ((float*)(s.ciT + c4 * 4 + 0))[r] = v.x;
            ((float*)(s.ciT + c4 * 4 + 1))[r] = v.y;
            ((float*)(s.ciT + c4 * 4 + 2))[r] = v.z;
            ((float*)(s.ciT + c4 * 4 + 3))[r] = v.w;
        }
    }
    __syncthreads();

    for (int t = 0; t < Td; t++) {
        // ---- P1: W1 on ciT (thr 0-511) || Wo_{t-1} on woT (thr 512-1023) ----
        if (tid < 512)
            gemm_main<Ed + Vd, Hd, 512>(tid, s.ciT, W1, b1, s.scratch);
        else if (t > 0)
            gemm_main<Cd + Vd, Od, 512>(tid - 512, s.woT, Wo, bo, s.scratch + 2048);
        __syncthreads();

        // ---- P2: combine h (+relu) | combine out_{t-1} -> global ----
        if (tid < 256)
            gemm_combine<Hd, 8, true, 1>(tid, s.scratch, nullptr, s.hT, 0);
        else if (tid < 512 && t > 0)
            gemm_combine<Od, 8, false, 2>(tid - 256, s.scratch + 2048,
                                          out + ((size_t)(t - 1) * Bd + b0) * Od,
                                          nullptr, (size_t)Od);
        __syncthreads();

        // ---- P3: co = h @ W2 + b2 (full width) ----
        gemm_main<Hd, Cd, NTH>(tid, s.hT, W2, b2, s.scratch);
        __syncthreads();
        if (tid < 256)
            gemm_combine<Cd, 16, false, 1>(tid, s.scratch, nullptr, s.woT, 0);
        __syncthreads();

        // ---- P4: k = co @ Wr (thr 0-511) || o = co @ Ww (thr 512-1023) ----
        if (tid < 512)
            gemm_main<Cd, Vd, 512>(tid, s.woT, Wr, br, s.scratch);
        else
            gemm_main<Cd, 2 * Vd, 512>(tid - 512, s.woT, Ww, bw, s.scratch + 2048);
        __syncthreads();

        // ---- P5: combine k | combine o ----
        if (tid < 256)
            gemm_combine<Vd, 8, false, 0>(tid, s.scratch, &s.k[0][0], nullptr, 0);
        else if (tid < 768)
            gemm_combine<2 * Vd, 4, false, 0>(tid - 256, s.scratch + 2048, &s.o[0][0], nullptr, 0);
        __syncthreads();

        // ==== P6: FUSED pass (f32x2): per-warp norms + deferred update + dots
        //          + online-softmax readout. warp: r = w>>3, j = w&7. ====
        {
            const int r = wid >> 3, j = wid & 7;
            const ulonglong2* k2 = (const ulonglong2*)s.k[r];
            const ulonglong2* q2 = (const ulonglong2*)s.o[r];
            const ulonglong2* v2 = (const ulonglong2*)s.vprev[r];
            ulonglong2 kA = k2[lane], kB = k2[lane + 32];
            ulonglong2 qA = q2[lane], qB = q2[lane + 32];
            ulonglong2 vA = v2[lane], vB = v2[lane + 32];

            // in-warp key norms (replicated across j-warps; barrier-free)
            float knr, kwnr;
            {
                u64 n2 = 0ull;
                FMA2(n2, kA.x, kA.x, n2); FMA2(n2, kA.y, kA.y, n2);
                FMA2(n2, kB.x, kB.x, n2); FMA2(n2, kB.y, kB.y, n2);
                float lo, hi; UPK2(lo, hi, n2);
                knr = fmaxf(sqrtf(wsum(lo + hi)), EPSf);
                n2 = 0ull;
                FMA2(n2, qA.x, qA.x, n2); FMA2(n2, qA.y, qA.y, n2);
                FMA2(n2, qB.x, qB.x, n2); FMA2(n2, qB.y, qB.y, n2);
                UPK2(lo, hi, n2);
                kwnr = fmaxf(sqrtf(wsum(lo + hi)), EPSf);
            }

            float M = -1e30f, Z = 0.f;
            u64 r0 = 0ull, r1 = 0ull, r2 = 0ull, r3 = 0ull;
            ulonglong2* gm = (ulonglong2*)(g_mem + (size_t)(b0 + r) * Nd * Vd);

            #pragma unroll 2
            for (int i = 0; i < Nd / 8; i++) {
                const int n = j + 8 * i;
                ulonglong2* mp = gm + (size_t)n * (Vd / 4);
                ulonglong2 m0 = mp[lane], m1 = mp[lane + 32];
                float wp = s.wwprev[r][n];
                u64 wp2; PK2(wp2, wp, wp);
                FMA2(m0.x, wp2, vA.x, m0.x); FMA2(m0.y, wp2, vA.y, m0.y);
                FMA2(m1.x, wp2, vB.x, m1.x); FMA2(m1.y, wp2, vB.y, m1.y);
                mp[lane] = m0; mp[lane + 32] = m1;

                u64 dk2 = 0ull, dw2 = 0ull, nn2 = 0ull;
                FMA2(dk2, m0.x, kA.x, dk2); FMA2(dk2, m0.y, kA.y, dk2);
                FMA2(dk2, m1.x, kB.x, dk2); FMA2(dk2, m1.y, kB.y, dk2);
                FMA2(dw2, m0.x, qA.x, dw2); FMA2(dw2, m0.y, qA.y, dw2);
                FMA2(dw2, m1.x, qB.x, dw2); FMA2(dw2, m1.y, qB.y, dw2);
                FMA2(nn2, m0.x, m0.x, nn2); FMA2(nn2, m0.y, m0.y, nn2);
                FMA2(nn2, m1.x, m1.x, nn2); FMA2(nn2, m1.y, m1.y, nn2);
                float lo, hi, dk, dw, nn;
                UPK2(lo, hi, dk2); dk = lo + hi;
                UPK2(lo, hi, dw2); dw = lo + hi;
                UPK2(lo, hi, nn2); nn = lo + hi;
                dk = wsum(dk); dw = wsum(dw); nn = wsum(nn);

                float mn = fmaxf(sqrtf(nn), EPSf);
                float sk = dk / (knr * mn);
                float sw = dw / (kwnr * mn);
                if (!lane) s.ww[r][n] = sw;

                float nM = fmaxf(M, sk);
                float sc = __expf(M - nM);
                float e  = __expf(sk - nM);
                Z = fmaf(Z, sc, e);
                u64 sc2, e2, tt;
                PK2(sc2, sc, sc); PK2(e2, e, e);
                MUL2(tt, e2, m0.x); FMA2(r0, r0, sc2, tt);
                MUL2(tt, e2, m0.y); FMA2(r1, r1, sc2, tt);
                MUL2(tt, e2, m1.x); FMA2(r2, r2, sc2, tt);
                MUL2(tt, e2, m1.y); FMA2(r3, r3, sc2, tt);
                M = nM;
            }
            ((ulonglong2*)s.scratch)[(r * 8 + j) * 64 + lane]      = make_ulonglong2(r0, r1);
            ((ulonglong2*)s.scratch)[(r * 8 + j) * 64 + lane + 32] = make_ulonglong2(r2, r3);
            if (!lane) { s.pM[r][j] = M; s.pZ[r][j] = Z; }
        }
        __syncthreads();

        // ---- P7: merge online-softmax partial scales (warp 0) ----
        if (wid == 0) {
            int r = lane >> 3, j = lane & 7;
            float m = s.pM[r][j];
            float mm = m;
            mm = fmaxf(mm, __shfl_xor_sync(0xffffffffu, mm, 1));
            mm = fmaxf(mm, __shfl_xor_sync(0xffffffffu, mm, 2));
            mm = fmaxf(mm, __shfl_xor_sync(0xffffffffu, mm, 4));
            float cf = __expf(m - mm);
            float zs = cf * s.pZ[r][j];
            zs += __shfl_xor_sync(0xffffffffu, zs, 1);
            zs += __shfl_xor_sync(0xffffffffu, zs, 2);
            zs += __shfl_xor_sync(0xffffffffu, zs, 4);
            s.coef[r][j] = cf;
            if (j == 0) s.invZ[r] = 1.f / zs;
        }
        __syncthreads();

        // ---- P8: r-combine | ww softmax | vprev copy | stage x_{t+1} ----
        if (tid < BT * Vd / 4) {
            int r = tid >> 6, c4 = tid & 63;
            float4 acc = make_float4(0.f, 0.f, 0.f, 0.f);
            #pragma unroll
            for (int j = 0; j < 8; j++) {
                float cf = s.coef[r][j];
                float4 p = s.scratch[(r * 8 + j) * 64 + c4];
                acc.x = fmaf(cf, p.x, acc.x); acc.y = fmaf(cf, p.y, acc.y);
                acc.z = fmaf(cf, p.z, acc.z); acc.w = fmaf(cf, p.w, acc.w);
            }
            float iz = s.invZ[r];
            acc.x *= iz; acc.y *= iz; acc.z *= iz; acc.w *= iz;
            ((float*)(s.woT + Cd + c4 * 4 + 0))[r] = acc.x;
            ((float*)(s.woT + Cd + c4 * 4 + 1))[r] = acc.y;
            ((float*)(s.woT + Cd + c4 * 4 + 2))[r] = acc.z;
            ((float*)(s.woT + Cd + c4 * 4 + 3))[r] = acc.w;
            ((float*)(s.ciT + Ed + c4 * 4 + 0))[r] = acc.x;
            ((float*)(s.ciT + Ed + c4 * 4 + 1))[r] = acc.y;
            ((float*)(s.ciT + Ed + c4 * 4 + 2))[r] = acc.z;
            ((float*)(s.ciT + Ed + c4 * 4 + 3))[r] = acc.w;
        } else if (wid >= 8 && wid < 8 + BT) {
            int r = wid - 8;
            float* rowp = s.ww[r];
            float v0 = rowp[lane], v1 = rowp[lane + 32], v2 = rowp[lane + 64], v3 = rowp[lane + 96];
            float mx = wmax(fmaxf(fmaxf(v0, v1), fmaxf(v2, v3)));
            float e0 = __expf(v0 - mx), e1 = __expf(v1 - mx), e2 = __expf(v2 - mx), e3 = __expf(v3 - mx);
            float sm = wsum(e0 + e1 + e2 + e3);
            float inv = 1.f / sm;
            s.wwprev[r][lane]      = e0 * inv;
            s.wwprev[r][lane + 32] = e1 * inv;
            s.wwprev[r][lane + 64] = e2 * inv;
            s.wwprev[r][lane + 96] = e3 * inv;
        } else if (tid >= 384 && tid < 640) {
            int idx = tid - 384;
            int r = idx >> 6, c4 = idx & 63;
            ((float4*)s.vprev[r])[c4] = ((const float4*)(s.o[r] + Vd))[c4];
        } else if (tid >= 640 && tid < 896 && t + 1 < Td) {
            int idx = tid - 640;
            int r = idx >> 6, c4 = idx & 63;
            float4 v = __ldg((const float4*)(x + ((size_t)(t + 1) * Bd + b0 + r) * Ed) + c4);
            ((float*)(s.ciT + c4 * 4 + 0))[r] = v.x;
            ((float*)(s.ciT + c4 * 4 + 1))[r] = v.y;
            ((float*)(s.ciT + c4 * 4 + 2))[r] = v.z;
            ((float*)(s.ciT + c4 * 4 + 3))[r] = v.w;
        }
        __syncthreads();
    }

    // ---- epilogue: out for t = Td-1 ----
    gemm_main<Cd + Vd, Od, NTH>(tid, s.woT, Wo, bo, s.scratch);
    __syncthreads();
    if (tid < 256)
        gemm_combine<Od, 16, false, 2>(tid, s.scratch,
                                       out + ((size_t)(Td - 1) * Bd + b0) * Od,
                                       nullptr, (size_t)Od);
}

extern "C" void kernel_launch(void* const* d_in, const int* in_sizes, int n_in,
                              void* d_out, int out_size)
{
    (void)in_sizes; (void)n_in; (void)out_size;
    const float* x         = (const float*)d_in[0];
    const float* W1        = (const float*)d_in[1];
    const float* b1        = (const float*)d_in[2];
    const float* W2        = (const float*)d_in[3];
    const float* b2        = (const float*)d_in[4];
    const float* Wr        = (const float*)d_in[5];
    const float* br        = (const float*)d_in[6];
    const float* Ww        = (const float*)d_in[7];
    const float* bw        = (const float*)d_in[8];
    const float* Wo        = (const float*)d_in[9];
    const float* bo        = (const float*)d_in[10];
    const float* init_read = (const float*)d_in[11];
    const float* mem0      = (const float*)d_in[12];
    float* out = (float*)d_out;

    int smem = (int)sizeof(SM);
    cudaFuncSetAttribute(ntm_kernel, cudaFuncAttributeMaxDynamicSharedMemorySize, smem);
    ntm_kernel<<<NCTA, NTH, smem>>>(x, W1, b1, W2, b2, Wr, br, Ww, bw, Wo, bo,
                                    init_read, mem0, out);
}